// round 11
// baseline (speedup 1.0000x reference)
#include <cuda_runtime.h>
#include <cuda_fp16.h>
#include <mma.h>
using namespace nvcuda;

#define NNODES 50000
#define NEDGES 800000
#define DIN 128
#define HC 256            // H*C
#define NH 4
#define CC 64
#define NG 512
#define NOUT 10
#define NEG 0.2f
#define EPSB 1e-5f
#define NB_SCAN 49        // ceil(50000/1024)

// ---------------- scratch (static device globals; no runtime alloc) ----------
__device__ __half g_h1h[NNODES * HC];    // GEMM1 output (fp16, gather source)
__device__ float  g_out1[NNODES * HC];   // layer1 aggregated output (fp32, GEMM2 A w/ fused BN)
__device__ __half g_h2h[NNODES * CC];    // GEMM2 output (fp16, gather source)
__device__ float g_als1[NNODES * 4];
__device__ float g_ald1[NNODES * 4];
__device__ float g_als2[NNODES];
__device__ float g_ald2[NNODES];
__device__ int   g_deg[NNODES];
__device__ int   g_rowptr[NNODES + 1];
__device__ int   g_cursor[NNODES];
__device__ int   g_csrc[NEDGES];
__device__ int   g_blksum[NB_SCAN];
__device__ float g_bnsum[HC];
__device__ float g_bnsq[HC];
__device__ float g_bnscale[HC];
__device__ float g_bnshift[HC];
__device__ float g_pool[NG * CC];
__device__ float g_cnt[NG];

__device__ __forceinline__ float lrelu(float x) { return x > 0.f ? x : NEG * x; }

// ---------------- setup ------------------------------------------------------
__global__ void zero_kernel() {
    int i = blockIdx.x * blockDim.x + threadIdx.x;
    if (i < NNODES) g_deg[i] = 0;
    if (i < NG * CC) g_pool[i] = 0.f;
    if (i < NG) g_cnt[i] = 0.f;
    if (i < HC) { g_bnsum[i] = 0.f; g_bnsq[i] = 0.f; }
}

__global__ void hist_kernel(const int* __restrict__ dst) {
    int i = blockIdx.x * blockDim.x + threadIdx.x;   // 8 edges per thread
    if (i * 8 < NEDGES) {
        int4 d0 = ((const int4*)dst)[i * 2];
        int4 d1 = ((const int4*)dst)[i * 2 + 1];
        atomicAdd(&g_deg[d0.x], 1);
        atomicAdd(&g_deg[d0.y], 1);
        atomicAdd(&g_deg[d0.z], 1);
        atomicAdd(&g_deg[d0.w], 1);
        atomicAdd(&g_deg[d1.x], 1);
        atomicAdd(&g_deg[d1.y], 1);
        atomicAdd(&g_deg[d1.z], 1);
        atomicAdd(&g_deg[d1.w], 1);
    }
}

// 3-phase exclusive scan over g_deg -> g_rowptr
__global__ void __launch_bounds__(1024) scanA_kernel() {
    __shared__ int warp_sums[32];
    int tid = threadIdx.x;
    int i = blockIdx.x * 1024 + tid;
    int lane = tid & 31, wid = tid >> 5;
    int v = (i < NNODES) ? g_deg[i] : 0;
    int incl = v;
#pragma unroll
    for (int off = 1; off < 32; off <<= 1) {
        int t = __shfl_up_sync(0xffffffffu, incl, off);
        if (lane >= off) incl += t;
    }
    if (lane == 31) warp_sums[wid] = incl;
    __syncthreads();
    if (wid == 0) {
        int s = warp_sums[lane];
#pragma unroll
        for (int off = 1; off < 32; off <<= 1) {
            int t = __shfl_up_sync(0xffffffffu, s, off);
            if (lane >= off) s += t;
        }
        warp_sums[lane] = s;
    }
    __syncthreads();
    int woff = (wid > 0) ? warp_sums[wid - 1] : 0;
    if (i < NNODES) g_rowptr[i] = woff + incl - v;
    if (tid == 1023) g_blksum[blockIdx.x] = woff + incl;
}

__global__ void scanB_kernel() {
    int lane = threadIdx.x;
    int acc = 0;
    for (int base = 0; base < NB_SCAN; base += 32) {
        int idx = base + lane;
        int v = (idx < NB_SCAN) ? g_blksum[idx] : 0;
        int incl = v;
#pragma unroll
        for (int off = 1; off < 32; off <<= 1) {
            int t = __shfl_up_sync(0xffffffffu, incl, off);
            if (lane >= off) incl += t;
        }
        if (idx < NB_SCAN) g_blksum[idx] = acc + incl - v;
        acc += __shfl_sync(0xffffffffu, incl, 31);
    }
    if (lane == 0) g_rowptr[NNODES] = acc;
}

__global__ void __launch_bounds__(1024) scanC_kernel() {
    int i = blockIdx.x * 1024 + threadIdx.x;
    if (i < NNODES) {
        int r = g_rowptr[i] + g_blksum[blockIdx.x];
        g_rowptr[i] = r;
        g_cursor[i] = r;
    }
}

__global__ void scatter_kernel(const int* __restrict__ src, const int* __restrict__ dst) {
    int i = blockIdx.x * blockDim.x + threadIdx.x;   // 8 edges per thread
    if (i * 8 < NEDGES) {
        int4 s0 = ((const int4*)src)[i * 2];
        int4 s1 = ((const int4*)src)[i * 2 + 1];
        int4 d0 = ((const int4*)dst)[i * 2];
        int4 d1 = ((const int4*)dst)[i * 2 + 1];
        int p0 = atomicAdd(&g_cursor[d0.x], 1);
        int p1 = atomicAdd(&g_cursor[d0.y], 1);
        int p2 = atomicAdd(&g_cursor[d0.z], 1);
        int p3 = atomicAdd(&g_cursor[d0.w], 1);
        int p4 = atomicAdd(&g_cursor[d1.x], 1);
        int p5 = atomicAdd(&g_cursor[d1.y], 1);
        int p6 = atomicAdd(&g_cursor[d1.z], 1);
        int p7 = atomicAdd(&g_cursor[d1.w], 1);
        g_csrc[p0] = s0.x; g_csrc[p1] = s0.y; g_csrc[p2] = s0.z; g_csrc[p3] = s0.w;
        g_csrc[p4] = s1.x; g_csrc[p5] = s1.y; g_csrc[p6] = s1.z; g_csrc[p7] = s1.w;
    }
}

// ---------------- tensor-core GEMMs ------------------------------------------
#define GBM 128
#define GBN 64
#define GBK 32

// fp32 A variant (GEMM1)
__global__ void __launch_bounds__(256) gemm_tc(const float* __restrict__ A,
                                               const float* __restrict__ B,
                                               __half* __restrict__ C,
                                               int M, int K, int N) {
    __shared__ __align__(16) __half As[GBM][GBK + 8];
    __shared__ __align__(16) __half Bs[GBK][GBN + 8];
    __shared__ __align__(16) float  Cst[8][16][20];

    int tid = threadIdx.x;
    int warp = tid >> 5;
    int lane = tid & 31;
    int wr = warp >> 1;
    int wc = warp & 1;
    int row0 = blockIdx.y * GBM;
    int col0 = blockIdx.x * GBN;

    wmma::fragment<wmma::accumulator, 16, 16, 16, float> acc[2][2];
#pragma unroll
    for (int i = 0; i < 2; i++)
#pragma unroll
        for (int j = 0; j < 2; j++) wmma::fill_fragment(acc[i][j], 0.f);

    for (int k0 = 0; k0 < K; k0 += GBK) {
#pragma unroll
        for (int l = 0; l < 2; l++) {
            int idx = tid + l * 256;
            int r = idx >> 2, q = idx & 3;
            int gr = row0 + r;
            float4 v0 = make_float4(0.f, 0.f, 0.f, 0.f);
            float4 v1 = v0;
            if (gr < M) {
                const float* p = A + (size_t)gr * K + k0 + q * 8;
                v0 = *(const float4*)p;
                v1 = *(const float4*)(p + 4);
            }
            __half2 h0 = __floats2half2_rn(v0.x, v0.y);
            __half2 h1 = __floats2half2_rn(v0.z, v0.w);
            __half2 h2 = __floats2half2_rn(v1.x, v1.y);
            __half2 h3 = __floats2half2_rn(v1.z, v1.w);
            uint4 u = make_uint4(*(unsigned*)&h0, *(unsigned*)&h1,
                                 *(unsigned*)&h2, *(unsigned*)&h3);
            *(uint4*)(&As[r][q * 8]) = u;
        }
        {
            int r = tid >> 3, q = tid & 7;
            const float* p = B + (size_t)(k0 + r) * N + col0 + q * 8;
            float4 v0 = *(const float4*)p;
            float4 v1 = *(const float4*)(p + 4);
            __half2 h0 = __floats2half2_rn(v0.x, v0.y);
            __half2 h1 = __floats2half2_rn(v0.z, v0.w);
            __half2 h2 = __floats2half2_rn(v1.x, v1.y);
            __half2 h3 = __floats2half2_rn(v1.z, v1.w);
            uint4 u = make_uint4(*(unsigned*)&h0, *(unsigned*)&h1,
                                 *(unsigned*)&h2, *(unsigned*)&h3);
            *(uint4*)(&Bs[r][q * 8]) = u;
        }
        __syncthreads();
#pragma unroll
        for (int kk = 0; kk < GBK; kk += 16) {
            wmma::fragment<wmma::matrix_a, 16, 16, 16, __half, wmma::row_major> af[2];
            wmma::fragment<wmma::matrix_b, 16, 16, 16, __half, wmma::row_major> bf[2];
#pragma unroll
            for (int i = 0; i < 2; i++)
                wmma::load_matrix_sync(af[i], &As[wr * 32 + i * 16][kk], GBK + 8);
#pragma unroll
            for (int j = 0; j < 2; j++)
                wmma::load_matrix_sync(bf[j], &Bs[kk][wc * 32 + j * 16], GBN + 8);
#pragma unroll
            for (int i = 0; i < 2; i++)
#pragma unroll
                for (int j = 0; j < 2; j++)
                    wmma::mma_sync(acc[i][j], af[i], bf[j], acc[i][j]);
        }
        __syncthreads();
    }
    int gr0 = row0 + wr * 32;
    int gc0 = col0 + wc * 32;
#pragma unroll
    for (int i = 0; i < 2; i++)
#pragma unroll
        for (int j = 0; j < 2; j++) {
            wmma::store_matrix_sync(&Cst[warp][0][0], acc[i][j], 20, wmma::mem_row_major);
            __syncwarp();
            int gr = gr0 + i * 16, gc = gc0 + j * 16;
#pragma unroll
            for (int e = lane; e < 128; e += 32) {
                int rr = e >> 3, cc = (e & 7) * 2;
                if (gr + rr < M) {
                    __half2 hv = __floats2half2_rn(Cst[warp][rr][cc], Cst[warp][rr][cc + 1]);
                    *(__half2*)(C + (size_t)(gr + rr) * N + gc + cc) = hv;
                }
            }
            __syncwarp();
        }
}

// GEMM2 with fused BN(scale/shift)+ReLU on A (A = g_out1 fp32)
__global__ void __launch_bounds__(256) gemm_tc_bn(const float* __restrict__ A,
                                                  const float* __restrict__ B,
                                                  __half* __restrict__ C,
                                                  int M, int K, int N) {
    __shared__ __align__(16) __half As[GBM][GBK + 8];
    __shared__ __align__(16) __half Bs[GBK][GBN + 8];
    __shared__ __align__(16) float  Cst[8][16][20];

    int tid = threadIdx.x;
    int warp = tid >> 5;
    int lane = tid & 31;
    int wr = warp >> 1;
    int wc = warp & 1;
    int row0 = blockIdx.y * GBM;
    int col0 = blockIdx.x * GBN;

    wmma::fragment<wmma::accumulator, 16, 16, 16, float> acc[2][2];
#pragma unroll
    for (int i = 0; i < 2; i++)
#pragma unroll
        for (int j = 0; j < 2; j++) wmma::fill_fragment(acc[i][j], 0.f);

    for (int k0 = 0; k0 < K; k0 += GBK) {
#pragma unroll
        for (int l = 0; l < 2; l++) {
            int idx = tid + l * 256;
            int r = idx >> 2, q = idx & 3;
            int gr = row0 + r;
            int kb = k0 + q * 8;
            float4 sc0 = *(const float4*)(g_bnscale + kb);
            float4 sc1 = *(const float4*)(g_bnscale + kb + 4);
            float4 sh0 = *(const float4*)(g_bnshift + kb);
            float4 sh1 = *(const float4*)(g_bnshift + kb + 4);
            float4 v0 = make_float4(0.f, 0.f, 0.f, 0.f);
            float4 v1 = v0;
            if (gr < M) {
                const float* p = A + (size_t)gr * K + kb;
                v0 = *(const float4*)p;
                v1 = *(const float4*)(p + 4);
            }
            v0.x = fmaxf(v0.x * sc0.x + sh0.x, 0.f);
            v0.y = fmaxf(v0.y * sc0.y + sh0.y, 0.f);
            v0.z = fmaxf(v0.z * sc0.z + sh0.z, 0.f);
            v0.w = fmaxf(v0.w * sc0.w + sh0.w, 0.f);
            v1.x = fmaxf(v1.x * sc1.x + sh1.x, 0.f);
            v1.y = fmaxf(v1.y * sc1.y + sh1.y, 0.f);
            v1.z = fmaxf(v1.z * sc1.z + sh1.z, 0.f);
            v1.w = fmaxf(v1.w * sc1.w + sh1.w, 0.f);
            if (gr >= M) { v0 = make_float4(0,0,0,0); v1 = v0; }
            __half2 h0 = __floats2half2_rn(v0.x, v0.y);
            __half2 h1 = __floats2half2_rn(v0.z, v0.w);
            __half2 h2 = __floats2half2_rn(v1.x, v1.y);
            __half2 h3 = __floats2half2_rn(v1.z, v1.w);
            uint4 u = make_uint4(*(unsigned*)&h0, *(unsigned*)&h1,
                                 *(unsigned*)&h2, *(unsigned*)&h3);
            *(uint4*)(&As[r][q * 8]) = u;
        }
        {
            int r = tid >> 3, q = tid & 7;
            const float* p = B + (size_t)(k0 + r) * N + col0 + q * 8;
            float4 v0 = *(const float4*)p;
            float4 v1 = *(const float4*)(p + 4);
            __half2 h0 = __floats2half2_rn(v0.x, v0.y);
            __half2 h1 = __floats2half2_rn(v0.z, v0.w);
            __half2 h2 = __floats2half2_rn(v1.x, v1.y);
            __half2 h3 = __floats2half2_rn(v1.z, v1.w);
            uint4 u = make_uint4(*(unsigned*)&h0, *(unsigned*)&h1,
                                 *(unsigned*)&h2, *(unsigned*)&h3);
            *(uint4*)(&Bs[r][q * 8]) = u;
        }
        __syncthreads();
#pragma unroll
        for (int kk = 0; kk < GBK; kk += 16) {
            wmma::fragment<wmma::matrix_a, 16, 16, 16, __half, wmma::row_major> af[2];
            wmma::fragment<wmma::matrix_b, 16, 16, 16, __half, wmma::row_major> bf[2];
#pragma unroll
            for (int i = 0; i < 2; i++)
                wmma::load_matrix_sync(af[i], &As[wr * 32 + i * 16][kk], GBK + 8);
#pragma unroll
            for (int j = 0; j < 2; j++)
                wmma::load_matrix_sync(bf[j], &Bs[kk][wc * 32 + j * 16], GBN + 8);
#pragma unroll
            for (int i = 0; i < 2; i++)
#pragma unroll
                for (int j = 0; j < 2; j++)
                    wmma::mma_sync(acc[i][j], af[i], bf[j], acc[i][j]);
        }
        __syncthreads();
    }
    int gr0 = row0 + wr * 32;
    int gc0 = col0 + wc * 32;
#pragma unroll
    for (int i = 0; i < 2; i++)
#pragma unroll
        for (int j = 0; j < 2; j++) {
            wmma::store_matrix_sync(&Cst[warp][0][0], acc[i][j], 20, wmma::mem_row_major);
            __syncwarp();
            int gr = gr0 + i * 16, gc = gc0 + j * 16;
#pragma unroll
            for (int e = lane; e < 128; e += 32) {
                int rr = e >> 3, cc = (e & 7) * 2;
                if (gr + rr < M) {
                    __half2 hv = __floats2half2_rn(Cst[warp][rr][cc], Cst[warp][rr][cc + 1]);
                    *(__half2*)(C + (size_t)(gr + rr) * N + gc + cc) = hv;
                }
            }
            __syncwarp();
        }
}

// ---------------- attention logits -------------------------------------------
__global__ void alpha1_kernel(const float* __restrict__ a_src, const float* __restrict__ a_dst) {
    int w = (blockIdx.x * blockDim.x + threadIdx.x) >> 5;
    int lane = threadIdx.x & 31;
    if (w >= NNODES) return;
    int c = lane * 8;
    uint4 u = *(const uint4*)(g_h1h + (long)w * HC + c);
    float2 f0 = __half22float2(*(__half2*)&u.x);
    float2 f1 = __half22float2(*(__half2*)&u.y);
    float2 f2 = __half22float2(*(__half2*)&u.z);
    float2 f3 = __half22float2(*(__half2*)&u.w);
    float4 s0 = *(const float4*)(a_src + c), s1 = *(const float4*)(a_src + c + 4);
    float4 d0 = *(const float4*)(a_dst + c), d1 = *(const float4*)(a_dst + c + 4);
    float ps = f0.x * s0.x + f0.y * s0.y + f1.x * s0.z + f1.y * s0.w
             + f2.x * s1.x + f2.y * s1.y + f3.x * s1.z + f3.y * s1.w;
    float pd = f0.x * d0.x + f0.y * d0.y + f1.x * d0.z + f1.y * d0.w
             + f2.x * d1.x + f2.y * d1.y + f3.x * d1.z + f3.y * d1.w;
#pragma unroll
    for (int off = 4; off; off >>= 1) {
        ps += __shfl_xor_sync(0xffffffffu, ps, off);
        pd += __shfl_xor_sync(0xffffffffu, pd, off);
    }
    if ((lane & 7) == 0) {
        g_als1[w * 4 + (lane >> 3)] = ps;
        g_ald1[w * 4 + (lane >> 3)] = pd;
    }
}

__global__ void alpha2_kernel(const float* __restrict__ a_src, const float* __restrict__ a_dst) {
    int w = (blockIdx.x * blockDim.x + threadIdx.x) >> 5;
    int lane = threadIdx.x & 31;
    if (w >= NNODES) return;
    int c = lane * 2;
    float2 h = __half22float2(*(const __half2*)(g_h2h + (long)w * CC + c));
    float2 sa = *(const float2*)(a_src + c);
    float2 da = *(const float2*)(a_dst + c);
    float ps = h.x * sa.x + h.y * sa.y;
    float pd = h.x * da.x + h.y * da.y;
#pragma unroll
    for (int off = 16; off; off >>= 1) {
        ps += __shfl_xor_sync(0xffffffffu, ps, off);
        pd += __shfl_xor_sync(0xffffffffu, pd, off);
    }
    if (lane == 0) { g_als2[w] = ps; g_ald2[w] = pd; }
}

// ---------------- layer-1 edge softmax + aggregation (warp per dst node) -----
__global__ void __launch_bounds__(256) edge1_kernel(const float* __restrict__ b1) {
    int w = (blockIdx.x * blockDim.x + threadIdx.x) >> 5;
    if (w >= NNODES) return;
    int lane = threadIdx.x & 31;
    int rs = g_rowptr[w], re = g_rowptr[w + 1];
    float4 ad = *(const float4*)(g_ald1 + 4 * w);
    float4 as = *(const float4*)(g_als1 + 4 * w);
    float m0 = lrelu(as.x + ad.x);
    float m1 = lrelu(as.y + ad.y);
    float m2 = lrelu(as.z + ad.z);
    float m3 = lrelu(as.w + ad.w);
    for (int i = rs + lane; i < re; i += 32) {
        int s = g_csrc[i];
        float4 a = *(const float4*)(g_als1 + 4 * s);
        m0 = fmaxf(m0, lrelu(a.x + ad.x));
        m1 = fmaxf(m1, lrelu(a.y + ad.y));
        m2 = fmaxf(m2, lrelu(a.z + ad.z));
        m3 = fmaxf(m3, lrelu(a.w + ad.w));
    }
#pragma unroll
    for (int off = 16; off; off >>= 1) {
        m0 = fmaxf(m0, __shfl_xor_sync(0xffffffffu, m0, off));
        m1 = fmaxf(m1, __shfl_xor_sync(0xffffffffu, m1, off));
        m2 = fmaxf(m2, __shfl_xor_sync(0xffffffffu, m2, off));
        m3 = fmaxf(m3, __shfl_xor_sync(0xffffffffu, m3, off));
    }
    int head = lane >> 3;
    float adh = (head == 0) ? ad.x : (head == 1) ? ad.y : (head == 2) ? ad.z : ad.w;
    float mh  = (head == 0) ? m0  : (head == 1) ? m1  : (head == 2) ? m2  : m3;
    float z = 0.f;
    float acc[8];
#pragma unroll
    for (int q = 0; q < 8; q++) acc[q] = 0.f;
    const int lc = lane * 8;
    for (int base = rs; base < re; base += 32) {
        int idx = base + lane;
        int myS = (idx < re) ? g_csrc[idx] : 0;
        int cnt = min(32, re - base);
        int j = 0;
        for (; j + 2 <= cnt; j += 2) {
            int s0 = __shfl_sync(0xffffffffu, myS, j);
            int s1 = __shfl_sync(0xffffffffu, myS, j + 1);
            float e0 = g_als1[4 * s0 + head] + adh;
            float e1 = g_als1[4 * s1 + head] + adh;
            uint4 u0 = *(const uint4*)(g_h1h + (long)s0 * HC + lc);
            uint4 u1 = *(const uint4*)(g_h1h + (long)s1 * HC + lc);
            e0 = e0 > 0.f ? e0 : NEG * e0;
            e1 = e1 > 0.f ? e1 : NEG * e1;
            float w0 = __expf(e0 - mh);
            float w1 = __expf(e1 - mh);
            z += w0 + w1;
            float2 a0 = __half22float2(*(__half2*)&u0.x);
            float2 a1 = __half22float2(*(__half2*)&u0.y);
            float2 a2 = __half22float2(*(__half2*)&u0.z);
            float2 a3 = __half22float2(*(__half2*)&u0.w);
            acc[0] += w0 * a0.x; acc[1] += w0 * a0.y;
            acc[2] += w0 * a1.x; acc[3] += w0 * a1.y;
            acc[4] += w0 * a2.x; acc[5] += w0 * a2.y;
            acc[6] += w0 * a3.x; acc[7] += w0 * a3.y;
            float2 c0 = __half22float2(*(__half2*)&u1.x);
            float2 c1 = __half22float2(*(__half2*)&u1.y);
            float2 c2 = __half22float2(*(__half2*)&u1.z);
            float2 c3 = __half22float2(*(__half2*)&u1.w);
            acc[0] += w1 * c0.x; acc[1] += w1 * c0.y;
            acc[2] += w1 * c1.x; acc[3] += w1 * c1.y;
            acc[4] += w1 * c2.x; acc[5] += w1 * c2.y;
            acc[6] += w1 * c3.x; acc[7] += w1 * c3.y;
        }
        if (j < cnt) {
            int s0 = __shfl_sync(0xffffffffu, myS, j);
            float e0 = g_als1[4 * s0 + head] + adh;
            uint4 u0 = *(const uint4*)(g_h1h + (long)s0 * HC + lc);
            e0 = e0 > 0.f ? e0 : NEG * e0;
            float w0 = __expf(e0 - mh);
            z += w0;
            float2 a0 = __half22float2(*(__half2*)&u0.x);
            float2 a1 = __half22float2(*(__half2*)&u0.y);
            float2 a2 = __half22float2(*(__half2*)&u0.z);
            float2 a3 = __half22float2(*(__half2*)&u0.w);
            acc[0] += w0 * a0.x; acc[1] += w0 * a0.y;
            acc[2] += w0 * a1.x; acc[3] += w0 * a1.y;
            acc[4] += w0 * a2.x; acc[5] += w0 * a2.y;
            acc[6] += w0 * a3.x; acc[7] += w0 * a3.y;
        }
    }
    {   // self loop
        float e0 = g_als1[4 * w + head] + adh;
        uint4 u0 = *(const uint4*)(g_h1h + (long)w * HC + lc);
        e0 = e0 > 0.f ? e0 : NEG * e0;
        float w0 = __expf(e0 - mh);
        z += w0;
        float2 a0 = __half22float2(*(__half2*)&u0.x);
        float2 a1 = __half22float2(*(__half2*)&u0.y);
        float2 a2 = __half22float2(*(__half2*)&u0.z);
        float2 a3 = __half22float2(*(__half2*)&u0.w);
        acc[0] += w0 * a0.x; acc[1] += w0 * a0.y;
        acc[2] += w0 * a1.x; acc[3] += w0 * a1.y;
        acc[4] += w0 * a2.x; acc[5] += w0 * a2.y;
        acc[6] += w0 * a3.x; acc[7] += w0 * a3.y;
    }
    float inv = 1.f / (z + 1e-16f);
    float4 o0 = make_float4(acc[0] * inv + b1[lc],     acc[1] * inv + b1[lc + 1],
                            acc[2] * inv + b1[lc + 2], acc[3] * inv + b1[lc + 3]);
    float4 o1 = make_float4(acc[4] * inv + b1[lc + 4], acc[5] * inv + b1[lc + 5],
                            acc[6] * inv + b1[lc + 6], acc[7] * inv + b1[lc + 7]);
    *(float4*)(g_out1 + (long)w * HC + lc) = o0;
    *(float4*)(g_out1 + (long)w * HC + lc + 4) = o1;
}

// ---------------- batchnorm --------------------------------------------------
__global__ void bn_stats_kernel() {
    int c = threadIdx.x;
    float s = 0.f, q = 0.f;
    for (int r = blockIdx.x; r < NNODES; r += gridDim.x) {
        float v = g_out1[(long)r * HC + c];
        s += v;
        q += v * v;
    }
    atomicAdd(&g_bnsum[c], s);
    atomicAdd(&g_bnsq[c], q);
}

__global__ void bn_finalize_kernel(const float* __restrict__ gamma, const float* __restrict__ beta) {
    int c = threadIdx.x;  // 256
    float invN = 1.f / (float)NNODES;
    float mean = g_bnsum[c] * invN;
    float var = g_bnsq[c] * invN - mean * mean;
    float sc = gamma[c] * rsqrtf(var + EPSB);
    g_bnscale[c] = sc;
    g_bnshift[c] = beta[c] - mean * sc;
}

// ---------------- layer-2 edge softmax + aggregation + pool ------------------
__global__ void __launch_bounds__(256) edge2_kernel(const float* __restrict__ b2,
                                                    const int* __restrict__ batch) {
    int w = (blockIdx.x * blockDim.x + threadIdx.x) >> 5;
    if (w >= NNODES) return;
    int lane = threadIdx.x & 31;
    int rs = g_rowptr[w], re = g_rowptr[w + 1];
    float ald = g_ald2[w];
    float m = lrelu(g_als2[w] + ald);
    for (int i = rs + lane; i < re; i += 32)
        m = fmaxf(m, lrelu(g_als2[g_csrc[i]] + ald));
#pragma unroll
    for (int off = 16; off; off >>= 1)
        m = fmaxf(m, __shfl_xor_sync(0xffffffffu, m, off));
    float z = 0.f, a0 = 0.f, a1 = 0.f;
    const int lc = lane * 2;
    for (int base = rs; base < re; base += 32) {
        int idx = base + lane;
        int myS = (idx < re) ? g_csrc[idx] : 0;
        int cnt = min(32, re - base);
        int j = 0;
        for (; j + 2 <= cnt; j += 2) {
            int s0 = __shfl_sync(0xffffffffu, myS, j);
            int s1 = __shfl_sync(0xffffffffu, myS, j + 1);
            float e0 = g_als2[s0] + ald;
            float e1 = g_als2[s1] + ald;
            float2 h0 = __half22float2(*(const __half2*)(g_h2h + (long)s0 * CC + lc));
            float2 h1 = __half22float2(*(const __half2*)(g_h2h + (long)s1 * CC + lc));
            e0 = e0 > 0.f ? e0 : NEG * e0;
            e1 = e1 > 0.f ? e1 : NEG * e1;
            float w0 = __expf(e0 - m);
            float w1 = __expf(e1 - m);
            z += w0 + w1;
            a0 += w0 * h0.x + w1 * h1.x;
            a1 += w0 * h0.y + w1 * h1.y;
        }
        if (j < cnt) {
            int s0 = __shfl_sync(0xffffffffu, myS, j);
            float e0 = g_als2[s0] + ald;
            float2 h0 = __half22float2(*(const __half2*)(g_h2h + (long)s0 * CC + lc));
            e0 = e0 > 0.f ? e0 : NEG * e0;
            float w0 = __expf(e0 - m);
            z += w0;
            a0 += w0 * h0.x;
            a1 += w0 * h0.y;
        }
    }
    {   // self loop
        float e0 = g_als2[w] + ald;
        float2 h0 = __half22float2(*(const __half2*)(g_h2h + (long)w * CC + lc));
        e0 = e0 > 0.f ? e0 : NEG * e0;
        float w0 = __expf(e0 - m);
        z += w0;
        a0 += w0 * h0.x;
        a1 += w0 * h0.y;
    }
    float inv = 1.f / (z + 1e-16f);
    float v0 = fmaxf(a0 * inv + b2[lc], 0.f);
    float v1 = fmaxf(a1 * inv + b2[lc + 1], 0.f);
    int g = batch[w];
    atomicAdd(&g_pool[g * CC + lc], v0);
    atomicAdd(&g_pool[g * CC + lc + 1], v1);
    if (lane == 0) atomicAdd(&g_cnt[g], 1.f);
}

// ---------------- classifier -------------------------------------------------
__global__ void cls_kernel(const float* __restrict__ cW1, const float* __restrict__ cb1,
                           const float* __restrict__ cW2, const float* __restrict__ cb2,
                           float* __restrict__ out) {
    int g = blockIdx.x;
    __shared__ float p[CC];
    __shared__ float hid[CC / 2];
    int t = threadIdx.x;
    float cnt = fmaxf(g_cnt[g], 1.f);
    p[t] = g_pool[g * CC + t] / cnt;
    __syncthreads();
    if (t < 32) {
        float s = cb1[t];
#pragma unroll
        for (int c = 0; c < CC; c++) s += p[c] * cW1[c * 32 + t];
        hid[t] = fmaxf(s, 0.f);
    }
    __syncthreads();
    if (t < NOUT) {
        float s = cb2[t];
#pragma unroll
        for (int j = 0; j < 32; j++) s += hid[j] * cW2[j * NOUT + t];
        out[g * NOUT + t] = s;
    }
}

// ---------------- launch -----------------------------------------------------
extern "C" void kernel_launch(void* const* d_in, const int* in_sizes, int n_in,
                              void* d_out, int out_size) {
    const float* x     = (const float*)d_in[0];
    const int*   ei    = (const int*)d_in[1];
    const int*   batch = (const int*)d_in[2];
    const float* W1    = (const float*)d_in[3];
    const float* as1   = (const float*)d_in[4];
    const float* ad1   = (const float*)d_in[5];
    const float* b1    = (const float*)d_in[6];
    const float* gamma = (const float*)d_in[7];
    const float* beta  = (const float*)d_in[8];
    const float* W2    = (const float*)d_in[9];
    const float* as2   = (const float*)d_in[10];
    const float* ad2   = (const float*)d_in[11];
    const float* b2    = (const float*)d_in[12];
    const float* cW1   = (const float*)d_in[13];
    const float* cb1   = (const float*)d_in[14];
    const float* cW2   = (const float*)d_in[15];
    const float* cb2   = (const float*)d_in[16];
    float* out = (float*)d_out;

    const int* src = ei;
    const int* dst = ei + NEDGES;

    float *out1p;
    __half *h1hp, *h2hp;
    cudaGetSymbolAddress((void**)&h1hp, g_h1h);
    cudaGetSymbolAddress((void**)&out1p, g_out1);
    cudaGetSymbolAddress((void**)&h2hp, g_h2h);

    // Lazy one-time infra (host-side objects only; no device memory).
    static cudaStream_t s1 = nullptr;
    static cudaEvent_t evA = nullptr, evB = nullptr;
    if (s1 == nullptr) {
        cudaStreamCreateWithFlags(&s1, cudaStreamNonBlocking);
        cudaEventCreateWithFlags(&evA, cudaEventDisableTiming);
        cudaEventCreateWithFlags(&evB, cudaEventDisableTiming);
    }

    const int EB8 = (NEDGES / 8 + 255) / 256;
    const int WB = (NNODES * 32 + 255) / 256;
    const int GY = (NNODES + GBM - 1) / GBM;

    // main stream: zeroing (needed by both branches)
    zero_kernel<<<(NNODES + 255) / 256, 256>>>();
    cudaEventRecord(evA, 0);

    // side stream: CSR build
    cudaStreamWaitEvent(s1, evA, 0);
    hist_kernel<<<EB8, 256, 0, s1>>>(dst);
    scanA_kernel<<<NB_SCAN, 1024, 0, s1>>>();
    scanB_kernel<<<1, 32, 0, s1>>>();
    scanC_kernel<<<NB_SCAN, 1024, 0, s1>>>();
    scatter_kernel<<<EB8, 256, 0, s1>>>(src, dst);
    cudaEventRecord(evB, s1);

    // main stream (concurrent with CSR build): GEMM1 + alpha1
    gemm_tc<<<dim3(HC / GBN, GY), 256>>>(x, W1, h1hp, NNODES, DIN, HC);
    alpha1_kernel<<<WB, 256>>>(as1, ad1);

    // join: edge1 needs CSR + alpha1
    cudaStreamWaitEvent(0, evB, 0);
    edge1_kernel<<<WB, 256>>>(b1);
    bn_stats_kernel<<<256, 256>>>();
    bn_finalize_kernel<<<1, 256>>>(gamma, beta);

    // layer 2 (BN+ReLU fused into GEMM2 A load)
    gemm_tc_bn<<<dim3(CC / GBN, GY), 256>>>(out1p, W2, h2hp, NNODES, HC, CC);
    alpha2_kernel<<<WB, 256>>>(as2, ad2);
    edge2_kernel<<<WB, 256>>>(b2, batch);

    // classifier
    cls_kernel<<<NG, 64>>>(cW1, cb1, cW2, cb2, out);
}

// round 12
// speedup vs baseline: 1.3431x; 1.3431x over previous
#include <cuda_runtime.h>
#include <cuda_fp16.h>
#include <mma.h>
using namespace nvcuda;

#define NNODES 50000
#define NEDGES 800000
#define DIN 128
#define HC 256            // H*C
#define NH 4
#define CC 64
#define NG 512
#define NOUT 10
#define NEG 0.2f
#define EPSB 1e-5f
#define NB_SCAN 49        // ceil(50000/1024)

// ---------------- scratch (static device globals; no runtime alloc) ----------
__device__ __half g_h1h[NNODES * HC];    // GEMM1 output (fp16, gather source)
__device__ float  g_out1[NNODES * HC];   // layer1 aggregated output (fp32, GEMM2 A w/ fused BN)
__device__ __half g_h2h[NNODES * CC];    // GEMM2 output (fp16, gather source)
__device__ float g_als1[NNODES * 4];
__device__ float g_ald1[NNODES * 4];
__device__ float g_als2[NNODES];
__device__ float g_ald2[NNODES];
__device__ int   g_deg[NNODES];
__device__ int   g_rowptr[NNODES + 1];
__device__ int   g_cursor[NNODES];
__device__ int   g_csrc[NEDGES];
__device__ int   g_blksum[NB_SCAN];
__device__ float g_bnsum[HC];
__device__ float g_bnsq[HC];
__device__ float g_bnscale[HC];
__device__ float g_bnshift[HC];
__device__ float g_pool[NG * CC];
__device__ float g_cnt[NG];

__device__ __forceinline__ float lrelu(float x) { return x > 0.f ? x : NEG * x; }

// ---------------- setup ------------------------------------------------------
__global__ void zero_kernel() {
    int i = blockIdx.x * blockDim.x + threadIdx.x;
    if (i < NNODES) g_deg[i] = 0;
    if (i < NG * CC) g_pool[i] = 0.f;
    if (i < NG) g_cnt[i] = 0.f;
    if (i < HC) { g_bnsum[i] = 0.f; g_bnsq[i] = 0.f; }
}

__global__ void hist_kernel(const int* __restrict__ dst) {
    int i = blockIdx.x * blockDim.x + threadIdx.x;   // 8 edges per thread
    if (i * 8 < NEDGES) {
        int4 d0 = ((const int4*)dst)[i * 2];
        int4 d1 = ((const int4*)dst)[i * 2 + 1];
        atomicAdd(&g_deg[d0.x], 1);
        atomicAdd(&g_deg[d0.y], 1);
        atomicAdd(&g_deg[d0.z], 1);
        atomicAdd(&g_deg[d0.w], 1);
        atomicAdd(&g_deg[d1.x], 1);
        atomicAdd(&g_deg[d1.y], 1);
        atomicAdd(&g_deg[d1.z], 1);
        atomicAdd(&g_deg[d1.w], 1);
    }
}

// 3-phase exclusive scan over g_deg -> g_rowptr
__global__ void __launch_bounds__(1024) scanA_kernel() {
    __shared__ int warp_sums[32];
    int tid = threadIdx.x;
    int i = blockIdx.x * 1024 + tid;
    int lane = tid & 31, wid = tid >> 5;
    int v = (i < NNODES) ? g_deg[i] : 0;
    int incl = v;
#pragma unroll
    for (int off = 1; off < 32; off <<= 1) {
        int t = __shfl_up_sync(0xffffffffu, incl, off);
        if (lane >= off) incl += t;
    }
    if (lane == 31) warp_sums[wid] = incl;
    __syncthreads();
    if (wid == 0) {
        int s = warp_sums[lane];
#pragma unroll
        for (int off = 1; off < 32; off <<= 1) {
            int t = __shfl_up_sync(0xffffffffu, s, off);
            if (lane >= off) s += t;
        }
        warp_sums[lane] = s;
    }
    __syncthreads();
    int woff = (wid > 0) ? warp_sums[wid - 1] : 0;
    if (i < NNODES) g_rowptr[i] = woff + incl - v;
    if (tid == 1023) g_blksum[blockIdx.x] = woff + incl;
}

__global__ void scanB_kernel() {
    int lane = threadIdx.x;
    int acc = 0;
    for (int base = 0; base < NB_SCAN; base += 32) {
        int idx = base + lane;
        int v = (idx < NB_SCAN) ? g_blksum[idx] : 0;
        int incl = v;
#pragma unroll
        for (int off = 1; off < 32; off <<= 1) {
            int t = __shfl_up_sync(0xffffffffu, incl, off);
            if (lane >= off) incl += t;
        }
        if (idx < NB_SCAN) g_blksum[idx] = acc + incl - v;
        acc += __shfl_sync(0xffffffffu, incl, 31);
    }
    if (lane == 0) g_rowptr[NNODES] = acc;
}

__global__ void __launch_bounds__(1024) scanC_kernel() {
    int i = blockIdx.x * 1024 + threadIdx.x;
    if (i < NNODES) {
        int r = g_rowptr[i] + g_blksum[blockIdx.x];
        g_rowptr[i] = r;
        g_cursor[i] = r;
    }
}

__global__ void scatter_kernel(const int* __restrict__ src, const int* __restrict__ dst) {
    int i = blockIdx.x * blockDim.x + threadIdx.x;   // 8 edges per thread
    if (i * 8 < NEDGES) {
        int4 s0 = ((const int4*)src)[i * 2];
        int4 s1 = ((const int4*)src)[i * 2 + 1];
        int4 d0 = ((const int4*)dst)[i * 2];
        int4 d1 = ((const int4*)dst)[i * 2 + 1];
        int p0 = atomicAdd(&g_cursor[d0.x], 1);
        int p1 = atomicAdd(&g_cursor[d0.y], 1);
        int p2 = atomicAdd(&g_cursor[d0.z], 1);
        int p3 = atomicAdd(&g_cursor[d0.w], 1);
        int p4 = atomicAdd(&g_cursor[d1.x], 1);
        int p5 = atomicAdd(&g_cursor[d1.y], 1);
        int p6 = atomicAdd(&g_cursor[d1.z], 1);
        int p7 = atomicAdd(&g_cursor[d1.w], 1);
        g_csrc[p0] = s0.x; g_csrc[p1] = s0.y; g_csrc[p2] = s0.z; g_csrc[p3] = s0.w;
        g_csrc[p4] = s1.x; g_csrc[p5] = s1.y; g_csrc[p6] = s1.z; g_csrc[p7] = s1.w;
    }
}

// ---------------- tensor-core GEMMs ------------------------------------------
#define GBM 128
#define GBN 64
#define GBK 32

// fp32 A variant (GEMM1)
__global__ void __launch_bounds__(256) gemm_tc(const float* __restrict__ A,
                                               const float* __restrict__ B,
                                               __half* __restrict__ C,
                                               int M, int K, int N) {
    __shared__ __align__(16) __half As[GBM][GBK + 8];
    __shared__ __align__(16) __half Bs[GBK][GBN + 8];
    __shared__ __align__(16) float  Cst[8][16][20];

    int tid = threadIdx.x;
    int warp = tid >> 5;
    int lane = tid & 31;
    int wr = warp >> 1;
    int wc = warp & 1;
    int row0 = blockIdx.y * GBM;
    int col0 = blockIdx.x * GBN;

    wmma::fragment<wmma::accumulator, 16, 16, 16, float> acc[2][2];
#pragma unroll
    for (int i = 0; i < 2; i++)
#pragma unroll
        for (int j = 0; j < 2; j++) wmma::fill_fragment(acc[i][j], 0.f);

    for (int k0 = 0; k0 < K; k0 += GBK) {
#pragma unroll
        for (int l = 0; l < 2; l++) {
            int idx = tid + l * 256;
            int r = idx >> 2, q = idx & 3;
            int gr = row0 + r;
            float4 v0 = make_float4(0.f, 0.f, 0.f, 0.f);
            float4 v1 = v0;
            if (gr < M) {
                const float* p = A + (size_t)gr * K + k0 + q * 8;
                v0 = *(const float4*)p;
                v1 = *(const float4*)(p + 4);
            }
            __half2 h0 = __floats2half2_rn(v0.x, v0.y);
            __half2 h1 = __floats2half2_rn(v0.z, v0.w);
            __half2 h2 = __floats2half2_rn(v1.x, v1.y);
            __half2 h3 = __floats2half2_rn(v1.z, v1.w);
            uint4 u = make_uint4(*(unsigned*)&h0, *(unsigned*)&h1,
                                 *(unsigned*)&h2, *(unsigned*)&h3);
            *(uint4*)(&As[r][q * 8]) = u;
        }
        {
            int r = tid >> 3, q = tid & 7;
            const float* p = B + (size_t)(k0 + r) * N + col0 + q * 8;
            float4 v0 = *(const float4*)p;
            float4 v1 = *(const float4*)(p + 4);
            __half2 h0 = __floats2half2_rn(v0.x, v0.y);
            __half2 h1 = __floats2half2_rn(v0.z, v0.w);
            __half2 h2 = __floats2half2_rn(v1.x, v1.y);
            __half2 h3 = __floats2half2_rn(v1.z, v1.w);
            uint4 u = make_uint4(*(unsigned*)&h0, *(unsigned*)&h1,
                                 *(unsigned*)&h2, *(unsigned*)&h3);
            *(uint4*)(&Bs[r][q * 8]) = u;
        }
        __syncthreads();
#pragma unroll
        for (int kk = 0; kk < GBK; kk += 16) {
            wmma::fragment<wmma::matrix_a, 16, 16, 16, __half, wmma::row_major> af[2];
            wmma::fragment<wmma::matrix_b, 16, 16, 16, __half, wmma::row_major> bf[2];
#pragma unroll
            for (int i = 0; i < 2; i++)
                wmma::load_matrix_sync(af[i], &As[wr * 32 + i * 16][kk], GBK + 8);
#pragma unroll
            for (int j = 0; j < 2; j++)
                wmma::load_matrix_sync(bf[j], &Bs[kk][wc * 32 + j * 16], GBN + 8);
#pragma unroll
            for (int i = 0; i < 2; i++)
#pragma unroll
                for (int j = 0; j < 2; j++)
                    wmma::mma_sync(acc[i][j], af[i], bf[j], acc[i][j]);
        }
        __syncthreads();
    }
    int gr0 = row0 + wr * 32;
    int gc0 = col0 + wc * 32;
#pragma unroll
    for (int i = 0; i < 2; i++)
#pragma unroll
        for (int j = 0; j < 2; j++) {
            wmma::store_matrix_sync(&Cst[warp][0][0], acc[i][j], 20, wmma::mem_row_major);
            __syncwarp();
            int gr = gr0 + i * 16, gc = gc0 + j * 16;
#pragma unroll
            for (int e = lane; e < 128; e += 32) {
                int rr = e >> 3, cc = (e & 7) * 2;
                if (gr + rr < M) {
                    __half2 hv = __floats2half2_rn(Cst[warp][rr][cc], Cst[warp][rr][cc + 1]);
                    *(__half2*)(C + (size_t)(gr + rr) * N + gc + cc) = hv;
                }
            }
            __syncwarp();
        }
}

// GEMM2 with fused BN(scale/shift)+ReLU on A (A = g_out1 fp32)
__global__ void __launch_bounds__(256) gemm_tc_bn(const float* __restrict__ A,
                                                  const float* __restrict__ B,
                                                  __half* __restrict__ C,
                                                  int M, int K, int N) {
    __shared__ __align__(16) __half As[GBM][GBK + 8];
    __shared__ __align__(16) __half Bs[GBK][GBN + 8];
    __shared__ __align__(16) float  Cst[8][16][20];

    int tid = threadIdx.x;
    int warp = tid >> 5;
    int lane = tid & 31;
    int wr = warp >> 1;
    int wc = warp & 1;
    int row0 = blockIdx.y * GBM;
    int col0 = blockIdx.x * GBN;

    wmma::fragment<wmma::accumulator, 16, 16, 16, float> acc[2][2];
#pragma unroll
    for (int i = 0; i < 2; i++)
#pragma unroll
        for (int j = 0; j < 2; j++) wmma::fill_fragment(acc[i][j], 0.f);

    for (int k0 = 0; k0 < K; k0 += GBK) {
#pragma unroll
        for (int l = 0; l < 2; l++) {
            int idx = tid + l * 256;
            int r = idx >> 2, q = idx & 3;
            int gr = row0 + r;
            int kb = k0 + q * 8;
            float4 sc0 = *(const float4*)(g_bnscale + kb);
            float4 sc1 = *(const float4*)(g_bnscale + kb + 4);
            float4 sh0 = *(const float4*)(g_bnshift + kb);
            float4 sh1 = *(const float4*)(g_bnshift + kb + 4);
            float4 v0 = make_float4(0.f, 0.f, 0.f, 0.f);
            float4 v1 = v0;
            if (gr < M) {
                const float* p = A + (size_t)gr * K + kb;
                v0 = *(const float4*)p;
                v1 = *(const float4*)(p + 4);
            }
            v0.x = fmaxf(v0.x * sc0.x + sh0.x, 0.f);
            v0.y = fmaxf(v0.y * sc0.y + sh0.y, 0.f);
            v0.z = fmaxf(v0.z * sc0.z + sh0.z, 0.f);
            v0.w = fmaxf(v0.w * sc0.w + sh0.w, 0.f);
            v1.x = fmaxf(v1.x * sc1.x + sh1.x, 0.f);
            v1.y = fmaxf(v1.y * sc1.y + sh1.y, 0.f);
            v1.z = fmaxf(v1.z * sc1.z + sh1.z, 0.f);
            v1.w = fmaxf(v1.w * sc1.w + sh1.w, 0.f);
            if (gr >= M) { v0 = make_float4(0,0,0,0); v1 = v0; }
            __half2 h0 = __floats2half2_rn(v0.x, v0.y);
            __half2 h1 = __floats2half2_rn(v0.z, v0.w);
            __half2 h2 = __floats2half2_rn(v1.x, v1.y);
            __half2 h3 = __floats2half2_rn(v1.z, v1.w);
            uint4 u = make_uint4(*(unsigned*)&h0, *(unsigned*)&h1,
                                 *(unsigned*)&h2, *(unsigned*)&h3);
            *(uint4*)(&As[r][q * 8]) = u;
        }
        {
            int r = tid >> 3, q = tid & 7;
            const float* p = B + (size_t)(k0 + r) * N + col0 + q * 8;
            float4 v0 = *(const float4*)p;
            float4 v1 = *(const float4*)(p + 4);
            __half2 h0 = __floats2half2_rn(v0.x, v0.y);
            __half2 h1 = __floats2half2_rn(v0.z, v0.w);
            __half2 h2 = __floats2half2_rn(v1.x, v1.y);
            __half2 h3 = __floats2half2_rn(v1.z, v1.w);
            uint4 u = make_uint4(*(unsigned*)&h0, *(unsigned*)&h1,
                                 *(unsigned*)&h2, *(unsigned*)&h3);
            *(uint4*)(&Bs[r][q * 8]) = u;
        }
        __syncthreads();
#pragma unroll
        for (int kk = 0; kk < GBK; kk += 16) {
            wmma::fragment<wmma::matrix_a, 16, 16, 16, __half, wmma::row_major> af[2];
            wmma::fragment<wmma::matrix_b, 16, 16, 16, __half, wmma::row_major> bf[2];
#pragma unroll
            for (int i = 0; i < 2; i++)
                wmma::load_matrix_sync(af[i], &As[wr * 32 + i * 16][kk], GBK + 8);
#pragma unroll
            for (int j = 0; j < 2; j++)
                wmma::load_matrix_sync(bf[j], &Bs[kk][wc * 32 + j * 16], GBN + 8);
#pragma unroll
            for (int i = 0; i < 2; i++)
#pragma unroll
                for (int j = 0; j < 2; j++)
                    wmma::mma_sync(acc[i][j], af[i], bf[j], acc[i][j]);
        }
        __syncthreads();
    }
    int gr0 = row0 + wr * 32;
    int gc0 = col0 + wc * 32;
#pragma unroll
    for (int i = 0; i < 2; i++)
#pragma unroll
        for (int j = 0; j < 2; j++) {
            wmma::store_matrix_sync(&Cst[warp][0][0], acc[i][j], 20, wmma::mem_row_major);
            __syncwarp();
            int gr = gr0 + i * 16, gc = gc0 + j * 16;
#pragma unroll
            for (int e = lane; e < 128; e += 32) {
                int rr = e >> 3, cc = (e & 7) * 2;
                if (gr + rr < M) {
                    __half2 hv = __floats2half2_rn(Cst[warp][rr][cc], Cst[warp][rr][cc + 1]);
                    *(__half2*)(C + (size_t)(gr + rr) * N + gc + cc) = hv;
                }
            }
            __syncwarp();
        }
}

// ---------------- attention logits -------------------------------------------
__global__ void alpha1_kernel(const float* __restrict__ a_src, const float* __restrict__ a_dst) {
    int w = (blockIdx.x * blockDim.x + threadIdx.x) >> 5;
    int lane = threadIdx.x & 31;
    if (w >= NNODES) return;
    int c = lane * 8;
    uint4 u = *(const uint4*)(g_h1h + (long)w * HC + c);
    float2 f0 = __half22float2(*(__half2*)&u.x);
    float2 f1 = __half22float2(*(__half2*)&u.y);
    float2 f2 = __half22float2(*(__half2*)&u.z);
    float2 f3 = __half22float2(*(__half2*)&u.w);
    float4 s0 = *(const float4*)(a_src + c), s1 = *(const float4*)(a_src + c + 4);
    float4 d0 = *(const float4*)(a_dst + c), d1 = *(const float4*)(a_dst + c + 4);
    float ps = f0.x * s0.x + f0.y * s0.y + f1.x * s0.z + f1.y * s0.w
             + f2.x * s1.x + f2.y * s1.y + f3.x * s1.z + f3.y * s1.w;
    float pd = f0.x * d0.x + f0.y * d0.y + f1.x * d0.z + f1.y * d0.w
             + f2.x * d1.x + f2.y * d1.y + f3.x * d1.z + f3.y * d1.w;
#pragma unroll
    for (int off = 4; off; off >>= 1) {
        ps += __shfl_xor_sync(0xffffffffu, ps, off);
        pd += __shfl_xor_sync(0xffffffffu, pd, off);
    }
    if ((lane & 7) == 0) {
        g_als1[w * 4 + (lane >> 3)] = ps;
        g_ald1[w * 4 + (lane >> 3)] = pd;
    }
}

__global__ void alpha2_kernel(const float* __restrict__ a_src, const float* __restrict__ a_dst) {
    int w = (blockIdx.x * blockDim.x + threadIdx.x) >> 5;
    int lane = threadIdx.x & 31;
    if (w >= NNODES) return;
    int c = lane * 2;
    float2 h = __half22float2(*(const __half2*)(g_h2h + (long)w * CC + c));
    float2 sa = *(const float2*)(a_src + c);
    float2 da = *(const float2*)(a_dst + c);
    float ps = h.x * sa.x + h.y * sa.y;
    float pd = h.x * da.x + h.y * da.y;
#pragma unroll
    for (int off = 16; off; off >>= 1) {
        ps += __shfl_xor_sync(0xffffffffu, ps, off);
        pd += __shfl_xor_sync(0xffffffffu, pd, off);
    }
    if (lane == 0) { g_als2[w] = ps; g_ald2[w] = pd; }
}

// ---------------- layer-1 edge softmax + aggregation (warp per dst node) -----
__global__ void __launch_bounds__(256) edge1_kernel(const float* __restrict__ b1) {
    int w = (blockIdx.x * blockDim.x + threadIdx.x) >> 5;
    if (w >= NNODES) return;
    int lane = threadIdx.x & 31;
    int rs = g_rowptr[w], re = g_rowptr[w + 1];
    float4 ad = *(const float4*)(g_ald1 + 4 * w);
    float4 as = *(const float4*)(g_als1 + 4 * w);
    float m0 = lrelu(as.x + ad.x);
    float m1 = lrelu(as.y + ad.y);
    float m2 = lrelu(as.z + ad.z);
    float m3 = lrelu(as.w + ad.w);
    for (int i = rs + lane; i < re; i += 32) {
        int s = g_csrc[i];
        float4 a = *(const float4*)(g_als1 + 4 * s);
        m0 = fmaxf(m0, lrelu(a.x + ad.x));
        m1 = fmaxf(m1, lrelu(a.y + ad.y));
        m2 = fmaxf(m2, lrelu(a.z + ad.z));
        m3 = fmaxf(m3, lrelu(a.w + ad.w));
    }
#pragma unroll
    for (int off = 16; off; off >>= 1) {
        m0 = fmaxf(m0, __shfl_xor_sync(0xffffffffu, m0, off));
        m1 = fmaxf(m1, __shfl_xor_sync(0xffffffffu, m1, off));
        m2 = fmaxf(m2, __shfl_xor_sync(0xffffffffu, m2, off));
        m3 = fmaxf(m3, __shfl_xor_sync(0xffffffffu, m3, off));
    }
    int head = lane >> 3;
    float adh = (head == 0) ? ad.x : (head == 1) ? ad.y : (head == 2) ? ad.z : ad.w;
    float mh  = (head == 0) ? m0  : (head == 1) ? m1  : (head == 2) ? m2  : m3;
    float z = 0.f;
    float acc[8];
#pragma unroll
    for (int q = 0; q < 8; q++) acc[q] = 0.f;
    const int lc = lane * 8;
    for (int base = rs; base < re; base += 32) {
        int idx = base + lane;
        int myS = (idx < re) ? g_csrc[idx] : 0;
        int cnt = min(32, re - base);
        int j = 0;
        for (; j + 2 <= cnt; j += 2) {
            int s0 = __shfl_sync(0xffffffffu, myS, j);
            int s1 = __shfl_sync(0xffffffffu, myS, j + 1);
            float e0 = g_als1[4 * s0 + head] + adh;
            float e1 = g_als1[4 * s1 + head] + adh;
            uint4 u0 = *(const uint4*)(g_h1h + (long)s0 * HC + lc);
            uint4 u1 = *(const uint4*)(g_h1h + (long)s1 * HC + lc);
            e0 = e0 > 0.f ? e0 : NEG * e0;
            e1 = e1 > 0.f ? e1 : NEG * e1;
            float w0 = __expf(e0 - mh);
            float w1 = __expf(e1 - mh);
            z += w0 + w1;
            float2 a0 = __half22float2(*(__half2*)&u0.x);
            float2 a1 = __half22float2(*(__half2*)&u0.y);
            float2 a2 = __half22float2(*(__half2*)&u0.z);
            float2 a3 = __half22float2(*(__half2*)&u0.w);
            acc[0] += w0 * a0.x; acc[1] += w0 * a0.y;
            acc[2] += w0 * a1.x; acc[3] += w0 * a1.y;
            acc[4] += w0 * a2.x; acc[5] += w0 * a2.y;
            acc[6] += w0 * a3.x; acc[7] += w0 * a3.y;
            float2 c0 = __half22float2(*(__half2*)&u1.x);
            float2 c1 = __half22float2(*(__half2*)&u1.y);
            float2 c2 = __half22float2(*(__half2*)&u1.z);
            float2 c3 = __half22float2(*(__half2*)&u1.w);
            acc[0] += w1 * c0.x; acc[1] += w1 * c0.y;
            acc[2] += w1 * c1.x; acc[3] += w1 * c1.y;
            acc[4] += w1 * c2.x; acc[5] += w1 * c2.y;
            acc[6] += w1 * c3.x; acc[7] += w1 * c3.y;
        }
        if (j < cnt) {
            int s0 = __shfl_sync(0xffffffffu, myS, j);
            float e0 = g_als1[4 * s0 + head] + adh;
            uint4 u0 = *(const uint4*)(g_h1h + (long)s0 * HC + lc);
            e0 = e0 > 0.f ? e0 : NEG * e0;
            float w0 = __expf(e0 - mh);
            z += w0;
            float2 a0 = __half22float2(*(__half2*)&u0.x);
            float2 a1 = __half22float2(*(__half2*)&u0.y);
            float2 a2 = __half22float2(*(__half2*)&u0.z);
            float2 a3 = __half22float2(*(__half2*)&u0.w);
            acc[0] += w0 * a0.x; acc[1] += w0 * a0.y;
            acc[2] += w0 * a1.x; acc[3] += w0 * a1.y;
            acc[4] += w0 * a2.x; acc[5] += w0 * a2.y;
            acc[6] += w0 * a3.x; acc[7] += w0 * a3.y;
        }
    }
    {   // self loop
        float e0 = g_als1[4 * w + head] + adh;
        uint4 u0 = *(const uint4*)(g_h1h + (long)w * HC + lc);
        e0 = e0 > 0.f ? e0 : NEG * e0;
        float w0 = __expf(e0 - mh);
        z += w0;
        float2 a0 = __half22float2(*(__half2*)&u0.x);
        float2 a1 = __half22float2(*(__half2*)&u0.y);
        float2 a2 = __half22float2(*(__half2*)&u0.z);
        float2 a3 = __half22float2(*(__half2*)&u0.w);
        acc[0] += w0 * a0.x; acc[1] += w0 * a0.y;
        acc[2] += w0 * a1.x; acc[3] += w0 * a1.y;
        acc[4] += w0 * a2.x; acc[5] += w0 * a2.y;
        acc[6] += w0 * a3.x; acc[7] += w0 * a3.y;
    }
    float inv = 1.f / (z + 1e-16f);
    float4 o0 = make_float4(acc[0] * inv + b1[lc],     acc[1] * inv + b1[lc + 1],
                            acc[2] * inv + b1[lc + 2], acc[3] * inv + b1[lc + 3]);
    float4 o1 = make_float4(acc[4] * inv + b1[lc + 4], acc[5] * inv + b1[lc + 5],
                            acc[6] * inv + b1[lc + 6], acc[7] * inv + b1[lc + 7]);
    *(float4*)(g_out1 + (long)w * HC + lc) = o0;
    *(float4*)(g_out1 + (long)w * HC + lc + 4) = o1;
}

// ---------------- batchnorm --------------------------------------------------
__global__ void bn_stats_kernel() {
    int c = threadIdx.x;
    float s = 0.f, q = 0.f;
    for (int r = blockIdx.x; r < NNODES; r += gridDim.x) {
        float v = g_out1[(long)r * HC + c];
        s += v;
        q += v * v;
    }
    atomicAdd(&g_bnsum[c], s);
    atomicAdd(&g_bnsq[c], q);
}

__global__ void bn_finalize_kernel(const float* __restrict__ gamma, const float* __restrict__ beta) {
    int c = threadIdx.x;  // 256
    float invN = 1.f / (float)NNODES;
    float mean = g_bnsum[c] * invN;
    float var = g_bnsq[c] * invN - mean * mean;
    float sc = gamma[c] * rsqrtf(var + EPSB);
    g_bnscale[c] = sc;
    g_bnshift[c] = beta[c] - mean * sc;
}

// ---------------- layer-2 edge softmax + aggregation + pool ------------------
__global__ void __launch_bounds__(256) edge2_kernel(const float* __restrict__ b2,
                                                    const int* __restrict__ batch) {
    int w = (blockIdx.x * blockDim.x + threadIdx.x) >> 5;
    if (w >= NNODES) return;
    int lane = threadIdx.x & 31;
    int rs = g_rowptr[w], re = g_rowptr[w + 1];
    float ald = g_ald2[w];
    float m = lrelu(g_als2[w] + ald);
    for (int i = rs + lane; i < re; i += 32)
        m = fmaxf(m, lrelu(g_als2[g_csrc[i]] + ald));
#pragma unroll
    for (int off = 16; off; off >>= 1)
        m = fmaxf(m, __shfl_xor_sync(0xffffffffu, m, off));
    float z = 0.f, a0 = 0.f, a1 = 0.f;
    const int lc = lane * 2;
    for (int base = rs; base < re; base += 32) {
        int idx = base + lane;
        int myS = (idx < re) ? g_csrc[idx] : 0;
        int cnt = min(32, re - base);
        int j = 0;
        for (; j + 2 <= cnt; j += 2) {
            int s0 = __shfl_sync(0xffffffffu, myS, j);
            int s1 = __shfl_sync(0xffffffffu, myS, j + 1);
            float e0 = g_als2[s0] + ald;
            float e1 = g_als2[s1] + ald;
            float2 h0 = __half22float2(*(const __half2*)(g_h2h + (long)s0 * CC + lc));
            float2 h1 = __half22float2(*(const __half2*)(g_h2h + (long)s1 * CC + lc));
            e0 = e0 > 0.f ? e0 : NEG * e0;
            e1 = e1 > 0.f ? e1 : NEG * e1;
            float w0 = __expf(e0 - m);
            float w1 = __expf(e1 - m);
            z += w0 + w1;
            a0 += w0 * h0.x + w1 * h1.x;
            a1 += w0 * h0.y + w1 * h1.y;
        }
        if (j < cnt) {
            int s0 = __shfl_sync(0xffffffffu, myS, j);
            float e0 = g_als2[s0] + ald;
            float2 h0 = __half22float2(*(const __half2*)(g_h2h + (long)s0 * CC + lc));
            e0 = e0 > 0.f ? e0 : NEG * e0;
            float w0 = __expf(e0 - m);
            z += w0;
            a0 += w0 * h0.x;
            a1 += w0 * h0.y;
        }
    }
    {   // self loop
        float e0 = g_als2[w] + ald;
        float2 h0 = __half22float2(*(const __half2*)(g_h2h + (long)w * CC + lc));
        e0 = e0 > 0.f ? e0 : NEG * e0;
        float w0 = __expf(e0 - m);
        z += w0;
        a0 += w0 * h0.x;
        a1 += w0 * h0.y;
    }
    float inv = 1.f / (z + 1e-16f);
    float v0 = fmaxf(a0 * inv + b2[lc], 0.f);
    float v1 = fmaxf(a1 * inv + b2[lc + 1], 0.f);
    int g = batch[w];
    atomicAdd(&g_pool[g * CC + lc], v0);
    atomicAdd(&g_pool[g * CC + lc + 1], v1);
    if (lane == 0) atomicAdd(&g_cnt[g], 1.f);
}

// ---------------- classifier -------------------------------------------------
__global__ void cls_kernel(const float* __restrict__ cW1, const float* __restrict__ cb1,
                           const float* __restrict__ cW2, const float* __restrict__ cb2,
                           float* __restrict__ out) {
    int g = blockIdx.x;
    __shared__ float p[CC];
    __shared__ float hid[CC / 2];
    int t = threadIdx.x;
    float cnt = fmaxf(g_cnt[g], 1.f);
    p[t] = g_pool[g * CC + t] / cnt;
    __syncthreads();
    if (t < 32) {
        float s = cb1[t];
#pragma unroll
        for (int c = 0; c < CC; c++) s += p[c] * cW1[c * 32 + t];
        hid[t] = fmaxf(s, 0.f);
    }
    __syncthreads();
    if (t < NOUT) {
        float s = cb2[t];
#pragma unroll
        for (int j = 0; j < 32; j++) s += hid[j] * cW2[j * NOUT + t];
        out[g * NOUT + t] = s;
    }
}

// ---------------- launch -----------------------------------------------------
extern "C" void kernel_launch(void* const* d_in, const int* in_sizes, int n_in,
                              void* d_out, int out_size) {
    const float* x     = (const float*)d_in[0];
    const int*   ei    = (const int*)d_in[1];
    const int*   batch = (const int*)d_in[2];
    const float* W1    = (const float*)d_in[3];
    const float* as1   = (const float*)d_in[4];
    const float* ad1   = (const float*)d_in[5];
    const float* b1    = (const float*)d_in[6];
    const float* gamma = (const float*)d_in[7];
    const float* beta  = (const float*)d_in[8];
    const float* W2    = (const float*)d_in[9];
    const float* as2   = (const float*)d_in[10];
    const float* ad2   = (const float*)d_in[11];
    const float* b2    = (const float*)d_in[12];
    const float* cW1   = (const float*)d_in[13];
    const float* cb1   = (const float*)d_in[14];
    const float* cW2   = (const float*)d_in[15];
    const float* cb2   = (const float*)d_in[16];
    float* out = (float*)d_out;

    const int* src = ei;
    const int* dst = ei + NEDGES;

    float *out1p;
    __half *h1hp, *h2hp;
    cudaGetSymbolAddress((void**)&h1hp, g_h1h);
    cudaGetSymbolAddress((void**)&out1p, g_out1);
    cudaGetSymbolAddress((void**)&h2hp, g_h2h);

    const int EB8 = (NEDGES / 8 + 255) / 256;
    const int WB = (NNODES * 32 + 255) / 256;
    const int GY = (NNODES + GBM - 1) / GBM;

    zero_kernel<<<(NNODES + 255) / 256, 256>>>();
    hist_kernel<<<EB8, 256>>>(dst);
    scanA_kernel<<<NB_SCAN, 1024>>>();
    scanB_kernel<<<1, 32>>>();
    scanC_kernel<<<NB_SCAN, 1024>>>();
    scatter_kernel<<<EB8, 256>>>(src, dst);

    // layer 1
    gemm_tc<<<dim3(HC / GBN, GY), 256>>>(x, W1, h1hp, NNODES, DIN, HC);
    alpha1_kernel<<<WB, 256>>>(as1, ad1);
    edge1_kernel<<<WB, 256>>>(b1);
    bn_stats_kernel<<<256, 256>>>();
    bn_finalize_kernel<<<1, 256>>>(gamma, beta);

    // layer 2 (BN+ReLU fused into GEMM2 A load)
    gemm_tc_bn<<<dim3(CC / GBN, GY), 256>>>(out1p, W2, h2hp, NNODES, HC, CC);
    alpha2_kernel<<<WB, 256>>>(as2, ad2);
    edge2_kernel<<<WB, 256>>>(b2, batch);

    // classifier
    cls_kernel<<<NG, 64>>>(cW1, cb1, cW2, cb2, out);
}